// round 1
// baseline (speedup 1.0000x reference)
#include <cuda_runtime.h>
#include <cuda_bf16.h>

// Problem constants
#define B_   65536
#define N_   64
#define NS_  8
#define G_   8
#define E_   16

#define THREADS_ 256
#define ROWS_    16            // rows per tile (16 threads per row)
#define NTILES_  (B_ / ROWS_)  // 4096
#define GRID_    608

// ---- shared memory layout (float offsets) ----
#define OFF_W1B1   0        // [n][e]{W1,b1} interleaved          2048
#define OFF_W2T    2048     // [e][n][f]                          16384
#define OFF_B2     18432    // [n][f]                             1024
#define OFF_QKVS   19456    // [s][e][j] j<48                     6144
#define OFF_BQKVS  25600    // [s][j]                             384
#define OFF_WOS    25984    // [s][e][f]                          2048
#define OFF_BOS    28032    // [s][f]                             128
#define OFF_WSYS   28160    // [s][k/2][f][2] (float2 pairs)      16384
#define OFF_BSYS   44544    // [s][f]                             128
#define OFF_QKVX   44672    // [e][j]                             768
#define OFF_BQKVX  45440    // [j]                                48
#define OFF_WOX    45488    // [e][f]                             256
#define OFF_BOX    45744    // [f]                                16
#define OFF_SIDX   45760    // 64 ints                            64
#define OFF_SCR    45824    // 16 rows x 576
#define SCR_ROW_   576      // per row: [0,64) x | [64,192) ebuf | [192,576) qkv/attn
#define SMEM_FLOATS (OFF_SCR + ROWS_ * SCR_ROW_)   // 55040
#define SMEM_BYTES  (SMEM_FLOATS * 4)              // 220160

// 8-token, E=16, H=4 multi-head self-attention for one row (16-thread group).
// Input tokens in ebuf[t*16+f]; output attended[t][f] in at[8].
// Uses qkvb (384 floats) as scratch. ebuf is clobbered (holds o at the end).
__device__ __forceinline__ void mha8(const float* __restrict__ sm,
                                     float* __restrict__ ebuf,
                                     float* __restrict__ qkvb,
                                     int wqkv, int bq, int wo, int bo,
                                     int f, float at[8])
{
    float q[8], k[8], v[8];
    {
        float bqv = sm[bq + f], bkv = sm[bq + 16 + f], bvv = sm[bq + 32 + f];
#pragma unroll
        for (int t = 0; t < 8; ++t) { q[t] = bqv; k[t] = bkv; v[t] = bvv; }
    }
#pragma unroll
    for (int e = 0; e < 16; ++e) {
        float wq = sm[wqkv + e * 48 + f];
        float wk = sm[wqkv + e * 48 + 16 + f];
        float wv = sm[wqkv + e * 48 + 32 + f];
#pragma unroll
        for (int t = 0; t < 8; ++t) {
            float me = ebuf[t * 16 + e];
            q[t] = fmaf(me, wq, q[t]);
            k[t] = fmaf(me, wk, k[t]);
            v[t] = fmaf(me, wv, v[t]);
        }
    }
    float* qb = qkvb;
    float* kb = qkvb + 128;
#pragma unroll
    for (int t = 0; t < 8; ++t) { qb[t * 16 + f] = q[t] * 0.5f; kb[t * 16 + f] = k[t]; }
    __syncwarp();

    const int h4 = (f >> 2) << 2;   // head base dim
    const int d  = f & 3;
    float p[2][8];
#pragma unroll
    for (int ii = 0; ii < 2; ++ii) {
        int i = d + ii * 4;
        float q0 = qb[i * 16 + h4 + 0];
        float q1 = qb[i * 16 + h4 + 1];
        float q2 = qb[i * 16 + h4 + 2];
        float q3 = qb[i * 16 + h4 + 3];
#pragma unroll
        for (int j = 0; j < 8; ++j) {
            const float* kr = kb + j * 16 + h4;
            p[ii][j] = fmaf(q0, kr[0], fmaf(q1, kr[1], fmaf(q2, kr[2], q3 * kr[3])));
        }
    }
    float inv[2];
#pragma unroll
    for (int ii = 0; ii < 2; ++ii) {
        float m = p[ii][0];
#pragma unroll
        for (int j = 1; j < 8; ++j) m = fmaxf(m, p[ii][j]);
        float sum = 0.f;
#pragma unroll
        for (int j = 0; j < 8; ++j) { p[ii][j] = __expf(p[ii][j] - m); sum += p[ii][j]; }
        inv[ii] = 1.0f / sum;
    }
    __syncwarp();   // all lanes done reading qb/kb before attn overwrites them
    float* ab = qkvb;  // attn[h][i][j], head stride 65 (conflict-free)
#pragma unroll
    for (int ii = 0; ii < 2; ++ii) {
        int i = d + ii * 4;
#pragma unroll
        for (int j = 0; j < 8; ++j) ab[(f >> 2) * 65 + i * 8 + j] = p[ii][j] * inv[ii];
    }
    __syncwarp();
    float o[8];
#pragma unroll
    for (int i = 0; i < 8; ++i) {
        const float* ar = ab + (f >> 2) * 65 + i * 8;
        float acc = ar[0] * v[0];
#pragma unroll
        for (int j = 1; j < 8; ++j) acc = fmaf(ar[j], v[j], acc);
        o[i] = acc;
    }
    __syncwarp();
#pragma unroll
    for (int i = 0; i < 8; ++i) ebuf[i * 16 + f] = o[i];
    __syncwarp();
    float bov = sm[bo + f];
#pragma unroll
    for (int t = 0; t < 8; ++t) at[t] = bov;
#pragma unroll
    for (int e = 0; e < 16; ++e) {
        float w = sm[wo + e * 16 + f];
#pragma unroll
        for (int t = 0; t < 8; ++t) at[t] = fmaf(ebuf[t * 16 + e], w, at[t]);
    }
    // caller must __syncwarp() before reusing ebuf
}

extern "C" __global__ void __launch_bounds__(THREADS_, 1)
bio_encoder_kernel(const float* __restrict__ x,
                   const int*   __restrict__ sys_idx,
                   const float* __restrict__ W1,  const float* __restrict__ b1,
                   const float* __restrict__ W2,  const float* __restrict__ b2,
                   const float* __restrict__ Wqkv_s, const float* __restrict__ bqkv_s,
                   const float* __restrict__ Wo_s,   const float* __restrict__ bo_s,
                   const float* __restrict__ Wsys,   const float* __restrict__ bsys,
                   const float* __restrict__ Wqkv_x, const float* __restrict__ bqkv_x,
                   const float* __restrict__ Wo_x,   const float* __restrict__ bo_x,
                   float* __restrict__ out, int write_all_sys)
{
    extern __shared__ float sm[];
    const int tid = threadIdx.x;

    // ---- stage weights into shared (once per block) ----
    for (int i = tid; i < 1024; i += THREADS_) {
        sm[OFF_W1B1 + 2 * i]     = W1[i];
        sm[OFF_W1B1 + 2 * i + 1] = b1[i];
    }
    for (int i = tid; i < 16384; i += THREADS_) {           // W2[n][f][e] -> [e][n][f]
        int n = i >> 8, fo = (i >> 4) & 15, e = i & 15;
        sm[OFF_W2T + e * 1024 + n * 16 + fo] = W2[i];
    }
    for (int i = tid; i < 1024; i += THREADS_) sm[OFF_B2 + i] = b2[i];
    for (int i = tid; i < 6144; i += THREADS_) {            // Wqkv_s[s][j][e] -> [s][e][j]
        int s = i / 768, r = i - s * 768, j = r >> 4, e = r & 15;
        sm[OFF_QKVS + s * 768 + e * 48 + j] = Wqkv_s[i];
    }
    for (int i = tid; i < 384; i += THREADS_) sm[OFF_BQKVS + i] = bqkv_s[i];
    for (int i = tid; i < 2048; i += THREADS_) {            // Wo_s[s][f][e] -> [s][e][f]
        int s = i >> 8, fo = (i >> 4) & 15, e = i & 15;
        sm[OFF_WOS + s * 256 + e * 16 + fo] = Wo_s[i];
    }
    for (int i = tid; i < 128; i += THREADS_) sm[OFF_BOS + i] = bo_s[i];
    for (int i = tid; i < 16384; i += THREADS_) {           // Wsys[s][f][k] -> [s][k/2][f][2]
        int s = i >> 11, fo = (i >> 7) & 15, kk = i & 127;
        sm[OFF_WSYS + s * 2048 + (kk >> 1) * 32 + fo * 2 + (kk & 1)] = Wsys[i];
    }
    for (int i = tid; i < 128; i += THREADS_) sm[OFF_BSYS + i] = bsys[i];
    for (int i = tid; i < 768; i += THREADS_) {             // Wqkv_x[j][e] -> [e][j]
        int j = i >> 4, e = i & 15;
        sm[OFF_QKVX + e * 48 + j] = Wqkv_x[i];
    }
    if (tid < 48)  sm[OFF_BQKVX + tid] = bqkv_x[tid];
    if (tid < 256) {                                        // Wo_x[f][e] -> [e][f]
        int fo = tid >> 4, e = tid & 15;
        sm[OFF_WOX + e * 16 + fo] = Wo_x[tid];
    }
    if (tid < 16)  sm[OFF_BOX + tid] = bo_x[tid];
    if (tid < 64)  ((int*)(sm + OFF_SIDX))[tid] = sys_idx[tid];
    __syncthreads();

    const int g = tid >> 4;         // row slot in tile
    const int f = tid & 15;         // embedding dim
    float* scr  = sm + OFF_SCR + g * SCR_ROW_;
    float* xrow = scr;
    float* ebuf = scr + 64;
    float* qkvb = scr + 192;
    const int* sidx = (const int*)(sm + OFF_SIDX);

    for (int tile = blockIdx.x; tile < NTILES_; tile += gridDim.x) {
        const int row = tile * ROWS_ + g;

        // load this row's 64 biomarkers
#pragma unroll
        for (int c = 0; c < 4; ++c) xrow[f + c * 16] = x[row * 64 + f + c * 16];
        __syncwarp();

        float se[8];
#pragma unroll 1
        for (int s = 0; s < 8; ++s) {
            // ---- per-biomarker MLP encode for this system's 8 biomarkers ----
            float eg[8];
#pragma unroll
            for (int gg2 = 0; gg2 < 8; ++gg2) {
                int n = sidx[s * 8 + gg2];
                float xv = xrow[n];
                float acc = sm[OFF_B2 + n * 16 + f];
                const float2* wb  = (const float2*)(sm + OFF_W1B1 + n * 32);
                const float*  w2p = sm + OFF_W2T + n * 16 + f;
#pragma unroll
                for (int e = 0; e < 16; ++e) {
                    float2 w = wb[e];
                    float h  = fmaxf(fmaf(w.x, xv, w.y), 0.f);
                    acc = fmaf(h, w2p[e * 1024], acc);
                }
                eg[gg2] = acc;
            }
#pragma unroll
            for (int t = 0; t < 8; ++t) ebuf[t * 16 + f] = eg[t];
            __syncwarp();

            // ---- per-system MHA ----
            float at[8];
            mha8(sm, ebuf, qkvb,
                 OFF_QKVS + s * 768, OFF_BQKVS + s * 48,
                 OFF_WOS + s * 256, OFF_BOS + s * 16, f, at);
            __syncwarp();
#pragma unroll
            for (int t = 0; t < 8; ++t) ebuf[t * 16 + f] = at[t];
            __syncwarp();

            // ---- system embedding: [128] -> [16] ----
            float acc = sm[OFF_BSYS + s * 16 + f];
            const float2* ws = (const float2*)(sm + OFF_WSYS + s * 2048 + f * 2);
            const float2* fb = (const float2*)ebuf;
#pragma unroll
            for (int kp = 0; kp < 64; ++kp) {
                float2 w  = ws[kp * 16];
                float2 fe = fb[kp];
                acc = fmaf(fe.x, w.x, fmaf(fe.y, w.y, acc));
            }
            se[s] = acc;
            __syncwarp();   // ebuf free for next system
        }

        // ---- all_sys output ----
        if (write_all_sys) {
#pragma unroll
            for (int s = 0; s < 8; ++s)
                out[B_ * 128 + row * 128 + s * 16 + f] = se[s];
        }

        // ---- cross-system MHA ----
#pragma unroll
        for (int s = 0; s < 8; ++s) ebuf[s * 16 + f] = se[s];
        __syncwarp();
        float it[8];
        mha8(sm, ebuf, qkvb, OFF_QKVX, OFF_BQKVX, OFF_WOX, OFF_BOX, f, it);
#pragma unroll
        for (int t = 0; t < 8; ++t) out[row * 128 + t * 16 + f] = it[t];
        __syncwarp();   // done with scratch before next tile
    }
}

extern "C" void kernel_launch(void* const* d_in, const int* in_sizes, int n_in,
                              void* d_out, int out_size) {
    const float* x      = (const float*)d_in[0];
    const int*   sidx   = (const int*)  d_in[1];
    const float* W1     = (const float*)d_in[2];
    const float* b1     = (const float*)d_in[3];
    const float* W2     = (const float*)d_in[4];
    const float* b2     = (const float*)d_in[5];
    const float* Wqkv_s = (const float*)d_in[6];
    const float* bqkv_s = (const float*)d_in[7];
    const float* Wo_s   = (const float*)d_in[8];
    const float* bo_s   = (const float*)d_in[9];
    const float* Wsys   = (const float*)d_in[10];
    const float* bsys   = (const float*)d_in[11];
    const float* Wqkv_x = (const float*)d_in[12];
    const float* bqkv_x = (const float*)d_in[13];
    const float* Wo_x   = (const float*)d_in[14];
    const float* bo_x   = (const float*)d_in[15];
    float* out = (float*)d_out;

    cudaFuncSetAttribute(bio_encoder_kernel,
                         cudaFuncAttributeMaxDynamicSharedMemorySize, SMEM_BYTES);

    int write_all_sys = (out_size >= 2 * B_ * 128) ? 1 : 0;

    bio_encoder_kernel<<<GRID_, THREADS_, SMEM_BYTES>>>(
        x, sidx, W1, b1, W2, b2, Wqkv_s, bqkv_s, Wo_s, bo_s,
        Wsys, bsys, Wqkv_x, bqkv_x, Wo_x, bo_x, out, write_all_sys);
}

// round 3
// speedup vs baseline: 1.5008x; 1.5008x over previous
#include <cuda_runtime.h>
#include <cuda_bf16.h>

// Problem constants
#define B_   65536
#define NS_  8
#define G_   8
#define E_   16

#define THREADS_ 256
#define ROWS_    64            // rows per tile (4 threads per row)
#define NTILES_  (B_ / ROWS_)  // 1024
#define GRID_    152

// ---- shared memory layout (float offsets) ----
#define O_W1B1  0        // [n][e]{W1,b1}                2048
#define O_W2T   2048     // [n][e][f]                    16384
#define O_B2    18432    // [n][f]                       1024
#define O_QKVS  19456    // [s][e][48]  (q-part *0.5)    6144
#define O_BQKVS 25600    // [s][48]     (q-part *0.5)    384
#define O_MF    25984    // [s][t][ep][f] fused Wo*Wsys  16384
#define O_CF    42368    // [s][f]                       128
#define O_QKVX  42496    // [e][48]     (q-part *0.5)    768
#define O_BQKVX 43264    // [48]        (q-part *0.5)    48
#define O_WOX   43312    // [e][f]                       256
#define O_BOX   43568    // [f]                          16
#define O_SIDX  43584    // 64 ints                      64
#define O_EB    43648    // 64 rows x SROW token scratch
#define SROW_   132
#define SMEM_FLOATS (O_EB + ROWS_ * SROW_)   // 52096
#define SMEM_BYTES  (SMEM_FLOATS * 4)        // 208384

// fused out-proj * system-embedding weights (per-launch precompute)
__device__ float g_M[NS_ * G_ * E_ * E_];   // [s][t][ep][f]
__device__ float g_C[NS_ * E_];             // [s][f]

#define LD4(dst, p) { float4 _t = *(const float4*)(p); \
    (dst)[0]=_t.x; (dst)[1]=_t.y; (dst)[2]=_t.z; (dst)[3]=_t.w; }
#define ST4(p, src) { *(float4*)(p) = make_float4((src)[0],(src)[1],(src)[2],(src)[3]); }

// ---------------------------------------------------------------------------
// Prep: M[s][t][ep][f] = sum_e Wo_s[s][e][ep] * Wsys[s][f][t*16+e]
//       C[s][f]        = bsys[s][f] + sum_{t,e} bo_s[s][e]*Wsys[s][f][t*16+e]
// ---------------------------------------------------------------------------
__global__ void bio_prep_kernel(const float* __restrict__ Wo_s,
                                const float* __restrict__ Wsys,
                                const float* __restrict__ bo_s,
                                const float* __restrict__ bsys)
{
    int idx = blockIdx.x * blockDim.x + threadIdx.x;   // 0..16383
    int s  = idx >> 11;
    int r  = idx & 2047;
    int t  = r >> 8;
    int ep = (r >> 4) & 15;
    int f  = r & 15;
    const float* wo = Wo_s + s * 256;                 // [e][ep]
    const float* ws = Wsys + s * 2048 + f * 128 + t * 16;  // [e]
    float acc = 0.f;
#pragma unroll
    for (int e = 0; e < 16; ++e)
        acc = fmaf(wo[e * 16 + ep], ws[e], acc);
    g_M[((s * 8 + t) * 16 + ep) * 16 + f] = acc;

    if (idx < 128) {
        int s2 = idx >> 4, f2 = idx & 15;
        float c = bsys[idx];
        const float* wsf = Wsys + s2 * 2048 + f2 * 128;
        const float* bo  = bo_s + s2 * 16;
        for (int k = 0; k < 128; ++k)
            c = fmaf(bo[k & 15], wsf[k], c);
        g_C[idx] = c;
    }
}

// ---------------------------------------------------------------------------
// Attention core for 8 tokens, E=16, H=4. Lane owns head l4 (f = 4*l4..4*l4+3).
// Tokens read from eb[t*16+e]; q-scale pre-folded into weights.
// Output o[t][d] = attention output (before out-proj), register-resident.
// ---------------------------------------------------------------------------
__device__ __forceinline__ void mha_core(const float* __restrict__ sm,
                                         const float* __restrict__ eb,
                                         int wbase, int bbase, int f0,
                                         float o[8][4])
{
    float q[8][4], k[8][4], v[8][4];
    {
        float bq[4], bk[4], bv[4];
        LD4(bq, sm + bbase + f0);
        LD4(bk, sm + bbase + 16 + f0);
        LD4(bv, sm + bbase + 32 + f0);
#pragma unroll
        for (int t = 0; t < 8; ++t)
#pragma unroll
            for (int d = 0; d < 4; ++d) { q[t][d] = bq[d]; k[t][d] = bk[d]; v[t][d] = bv[d]; }
    }
#pragma unroll
    for (int e = 0; e < 16; e += 2) {
        float wqa[4], wka[4], wva[4], wqb[4], wkb[4], wvb[4];
        LD4(wqa, sm + wbase + e * 48 + f0);
        LD4(wka, sm + wbase + e * 48 + 16 + f0);
        LD4(wva, sm + wbase + e * 48 + 32 + f0);
        LD4(wqb, sm + wbase + (e + 1) * 48 + f0);
        LD4(wkb, sm + wbase + (e + 1) * 48 + 16 + f0);
        LD4(wvb, sm + wbase + (e + 1) * 48 + 32 + f0);
#pragma unroll
        for (int t = 0; t < 8; ++t) {
            float2 me = *(const float2*)(eb + t * 16 + e);
#pragma unroll
            for (int d = 0; d < 4; ++d) {
                q[t][d] = fmaf(me.x, wqa[d], fmaf(me.y, wqb[d], q[t][d]));
                k[t][d] = fmaf(me.x, wka[d], fmaf(me.y, wkb[d], k[t][d]));
                v[t][d] = fmaf(me.x, wva[d], fmaf(me.y, wvb[d], v[t][d]));
            }
        }
    }
    // scores + softmax + AV fully in registers (lane = one head)
#pragma unroll
    for (int i = 0; i < 8; ++i) {
        float sc[8];
#pragma unroll
        for (int j = 0; j < 8; ++j)
            sc[j] = fmaf(q[i][0], k[j][0], fmaf(q[i][1], k[j][1],
                    fmaf(q[i][2], k[j][2], q[i][3] * k[j][3])));
        float m = sc[0];
#pragma unroll
        for (int j = 1; j < 8; ++j) m = fmaxf(m, sc[j]);
        float w[8]; float sum = 0.f;
#pragma unroll
        for (int j = 0; j < 8; ++j) { w[j] = __expf(sc[j] - m); sum += w[j]; }
        float inv = __fdividef(1.f, sum);
#pragma unroll
        for (int d = 0; d < 4; ++d) o[i][d] = 0.f;
#pragma unroll
        for (int j = 0; j < 8; ++j) {
            float a = w[j] * inv;
#pragma unroll
            for (int d = 0; d < 4; ++d) o[i][d] = fmaf(a, v[j][d], o[i][d]);
        }
    }
}

// ---------------------------------------------------------------------------
extern "C" __global__ void __launch_bounds__(THREADS_, 1)
bio_encoder_kernel(const float* __restrict__ x,
                   const int*   __restrict__ sys_idx,
                   const float* __restrict__ W1,  const float* __restrict__ b1,
                   const float* __restrict__ W2,  const float* __restrict__ b2,
                   const float* __restrict__ Wqkv_s, const float* __restrict__ bqkv_s,
                   const float* __restrict__ Wqkv_x, const float* __restrict__ bqkv_x,
                   const float* __restrict__ Wo_x,   const float* __restrict__ bo_x,
                   float* __restrict__ out, int write_all_sys)
{
    extern __shared__ float sm[];
    const int tid = threadIdx.x;

    // ---- stage weights (once per block) ----
    for (int i = tid; i < 1024; i += THREADS_) {
        sm[O_W1B1 + 2 * i]     = W1[i];
        sm[O_W1B1 + 2 * i + 1] = b1[i];
    }
    for (int i = tid; i < 16384; i += THREADS_) {      // W2[n][f][e] -> [n][e][f]
        int n = i >> 8, e = (i >> 4) & 15, f = i & 15;
        sm[O_W2T + i] = W2[n * 256 + f * 16 + e];
    }
    for (int i = tid; i < 1024; i += THREADS_) sm[O_B2 + i] = b2[i];
    for (int i = tid; i < 6144; i += THREADS_) {       // Wqkv_s[s][j][e] -> [s][e][j]
        int s = i / 768, r = i - s * 768, e = r / 48, j = r - e * 48;
        float v = Wqkv_s[s * 768 + j * 16 + e];
        if (j < 16) v *= 0.5f;
        sm[O_QKVS + i] = v;
    }
    for (int i = tid; i < 384; i += THREADS_) {
        float v = bqkv_s[i];
        if ((i % 48) < 16) v *= 0.5f;
        sm[O_BQKVS + i] = v;
    }
    for (int i = tid; i < 16384; i += THREADS_) sm[O_MF + i] = g_M[i];
    for (int i = tid; i < 128;   i += THREADS_) sm[O_CF + i] = g_C[i];
    for (int i = tid; i < 768; i += THREADS_) {        // Wqkv_x[j][e] -> [e][j]
        int e = i / 48, j = i - e * 48;
        float v = Wqkv_x[j * 16 + e];
        if (j < 16) v *= 0.5f;
        sm[O_QKVX + i] = v;
    }
    if (tid < 48) { float v = bqkv_x[tid]; if (tid < 16) v *= 0.5f; sm[O_BQKVX + tid] = v; }
    if (tid < 256) {                                   // Wo_x[f][e] -> [e][f]
        int e = tid >> 4, f = tid & 15;
        sm[O_WOX + e * 16 + f] = Wo_x[f * 16 + e];
    }
    if (tid < 16) sm[O_BOX + tid] = bo_x[tid];
    if (tid < 64) ((int*)(sm + O_SIDX))[tid] = sys_idx[tid];
    __syncthreads();

    const int grp = tid >> 2;          // row slot 0..63
    const int f0  = (tid & 3) * 4;     // this lane's 4 f-dims == one head
    float* eb = sm + O_EB + grp * SROW_;
    const int* sidx = (const int*)(sm + O_SIDX);

    for (int tile = blockIdx.x; tile < NTILES_; tile += gridDim.x) {
        const int row = tile * ROWS_ + grp;
        const float* xr = x + row * 64;

        float se[8][4];

#pragma unroll 1
        for (int s = 0; s < 8; ++s) {
            // ---- gather this system's x values ----
            float xv[8];
#pragma unroll
            for (int t = 0; t < 8; ++t) xv[t] = xr[sidx[s * 8 + t]];

            // ---- per-biomarker MLP (lane computes its 4 f's) ----
#pragma unroll
            for (int t = 0; t < 8; ++t) {
                const int n = sidx[s * 8 + t];
                float acc[4];
                LD4(acc, sm + O_B2 + n * 16 + f0);
                const float* wb = sm + O_W1B1 + n * 32;
                const float* w2 = sm + O_W2T + n * 256 + f0;
                const float xvt = xv[t];
#pragma unroll
                for (int e = 0; e < 16; ++e) {
                    float2 w = *(const float2*)(wb + 2 * e);
                    float h  = fmaxf(fmaf(w.x, xvt, w.y), 0.f);
                    float ww[4];
                    LD4(ww, w2 + e * 16);
#pragma unroll
                    for (int d = 0; d < 4; ++d) acc[d] = fmaf(h, ww[d], acc[d]);
                }
                ST4(eb + t * 16 + f0, acc);
            }
            __syncwarp();

            // ---- per-system MHA (attention core in registers) ----
            float o[8][4];
            mha_core(sm, eb, O_QKVS + s * 768, O_BQKVS + s * 48, f0, o);
            __syncwarp();                       // everyone done reading eb
#pragma unroll
            for (int t = 0; t < 8; ++t) ST4(eb + t * 16 + f0, o[t]);
            __syncwarp();

            // ---- fused out-proj + system embedding ----
            float accs[4];
            LD4(accs, sm + O_CF + s * 16 + f0);
            const float* mb = sm + O_MF + s * 2048;
#pragma unroll
            for (int t = 0; t < 8; ++t) {
#pragma unroll
                for (int c4 = 0; c4 < 4; ++c4) {
                    float ov[4];
                    LD4(ov, eb + t * 16 + c4 * 4);
#pragma unroll
                    for (int c = 0; c < 4; ++c) {
                        float mw[4];
                        LD4(mw, mb + t * 256 + (c4 * 4 + c) * 16 + f0);
#pragma unroll
                        for (int d = 0; d < 4; ++d)
                            accs[d] = fmaf(ov[c], mw[d], accs[d]);
                    }
                }
            }
#pragma unroll
            for (int d = 0; d < 4; ++d) se[s][d] = accs[d];
            __syncwarp();                       // eb free for next system
        }

        // ---- all_sys output ----
        if (write_all_sys) {
#pragma unroll
            for (int s = 0; s < 8; ++s)
                ST4(out + (size_t)B_ * 128 + (size_t)row * 128 + s * 16 + f0, se[s]);
        }

        // ---- cross-system MHA ----
#pragma unroll
        for (int s = 0; s < 8; ++s) ST4(eb + s * 16 + f0, se[s]);
        __syncwarp();
        float o[8][4];
        mha_core(sm, eb, O_QKVX, O_BQKVX, f0, o);
        __syncwarp();
#pragma unroll
        for (int t = 0; t < 8; ++t) ST4(eb + t * 16 + f0, o[t]);
        __syncwarp();

        // ---- cross out-proj ----
        float at[8][4];
        {
            float bo[4];
            LD4(bo, sm + O_BOX + f0);
#pragma unroll
            for (int t = 0; t < 8; ++t)
#pragma unroll
                for (int d = 0; d < 4; ++d) at[t][d] = bo[d];
        }
#pragma unroll
        for (int e = 0; e < 16; e += 2) {
            float wa[4], wb2[4];
            LD4(wa,  sm + O_WOX + e * 16 + f0);
            LD4(wb2, sm + O_WOX + (e + 1) * 16 + f0);
#pragma unroll
            for (int t = 0; t < 8; ++t) {
                float2 ov = *(const float2*)(eb + t * 16 + e);
#pragma unroll
                for (int d = 0; d < 4; ++d)
                    at[t][d] = fmaf(ov.x, wa[d], fmaf(ov.y, wb2[d], at[t][d]));
            }
        }
#pragma unroll
        for (int t = 0; t < 8; ++t)
            ST4(out + (size_t)row * 128 + t * 16 + f0, at[t]);
        __syncwarp();   // eb reuse next tile
    }
}

extern "C" void kernel_launch(void* const* d_in, const int* in_sizes, int n_in,
                              void* d_out, int out_size) {
    const float* x      = (const float*)d_in[0];
    const int*   sidx   = (const int*)  d_in[1];
    const float* W1     = (const float*)d_in[2];
    const float* b1     = (const float*)d_in[3];
    const float* W2     = (const float*)d_in[4];
    const float* b2     = (const float*)d_in[5];
    const float* Wqkv_s = (const float*)d_in[6];
    const float* bqkv_s = (const float*)d_in[7];
    const float* Wo_s   = (const float*)d_in[8];
    const float* bo_s   = (const float*)d_in[9];
    const float* Wsys   = (const float*)d_in[10];
    const float* bsys   = (const float*)d_in[11];
    const float* Wqkv_x = (const float*)d_in[12];
    const float* bqkv_x = (const float*)d_in[13];
    const float* Wo_x   = (const float*)d_in[14];
    const float* bo_x   = (const float*)d_in[15];
    float* out = (float*)d_out;

    bio_prep_kernel<<<64, 256>>>(Wo_s, Wsys, bo_s, bsys);

    cudaFuncSetAttribute(bio_encoder_kernel,
                         cudaFuncAttributeMaxDynamicSharedMemorySize, SMEM_BYTES);

    int write_all_sys = (out_size >= 2 * B_ * 128) ? 1 : 0;

    bio_encoder_kernel<<<GRID_, THREADS_, SMEM_BYTES>>>(
        x, sidx, W1, b1, W2, b2, Wqkv_s, bqkv_s,
        Wqkv_x, bqkv_x, Wo_x, bo_x, out, write_all_sys);
}